// round 1
// baseline (speedup 1.0000x reference)
#include <cuda_runtime.h>
#include <cuda_bf16.h>
#include <stdint.h>

// Problem constants
#define B_    8
#define L_    4096
#define D_    1024
#define A_    256
#define LC_   4352      // A_ + L_
#define KEEP_ 256

// -------- scratch (no allocation allowed -> device globals) --------
__device__ float g_sal[B_ * LC_];
__device__ float g_totsum[B_ * D_];
__device__ float g_keptsum[B_ * D_];
__device__ int   g_topidx[B_ * KEEP_];
__device__ float g_ctx[B_ * D_];
__device__ float g_proj[B_ * D_];

// ---------------- K0: zero accumulators ----------------
__global__ void k_zero() {
    int i = blockIdx.x * blockDim.x + threadIdx.x;
    if (i < B_ * D_) { g_totsum[i] = 0.f; g_keptsum[i] = 0.f; }
}

// ---------------- K1: salience + total column sum ----------------
// grid: (32, B_), block 256 (8 warps). rows/block = 136, rows/warp = 17.
#define ROWS_PER_WARP 17
__global__ void k_salience(const float* __restrict__ x,
                           const float* __restrict__ active,
                           const float* __restrict__ wsal) {
    __shared__ float s_col[D_];
    const int b    = blockIdx.y;
    const int tid  = threadIdx.x;
    const int warp = tid >> 5;
    const int lane = tid & 31;

    for (int i = tid; i < D_; i += blockDim.x) s_col[i] = 0.f;

    float4 ws[8];
#pragma unroll
    for (int k = 0; k < 8; k++)
        ws[k] = *(const float4*)(wsal + k * 128 + lane * 4);
    float4 cs[8];
#pragma unroll
    for (int k = 0; k < 8; k++) cs[k] = make_float4(0.f, 0.f, 0.f, 0.f);

    __syncthreads();

    const int row0 = blockIdx.x * (8 * ROWS_PER_WARP) + warp * ROWS_PER_WARP;
    for (int r = 0; r < ROWS_PER_WARP; r++) {
        const int t = row0 + r;
        const float* src = (t < A_)
            ? active + ((size_t)b * A_ + t) * D_
            : x      + ((size_t)b * L_ + (t - A_)) * D_;
        float dot = 0.f;
#pragma unroll
        for (int k = 0; k < 8; k++) {
            float4 v = *(const float4*)(src + k * 128 + lane * 4);
            dot += v.x * ws[k].x + v.y * ws[k].y + v.z * ws[k].z + v.w * ws[k].w;
            cs[k].x += v.x; cs[k].y += v.y; cs[k].z += v.z; cs[k].w += v.w;
        }
#pragma unroll
        for (int o = 16; o > 0; o >>= 1)
            dot += __shfl_down_sync(0xffffffffu, dot, o);
        if (lane == 0) g_sal[b * LC_ + t] = dot;
    }

    // warp-private column sums -> shared -> 1 global RED per d per block
#pragma unroll
    for (int k = 0; k < 8; k++) {
        int d0 = k * 128 + lane * 4;
        atomicAdd(&s_col[d0 + 0], cs[k].x);
        atomicAdd(&s_col[d0 + 1], cs[k].y);
        atomicAdd(&s_col[d0 + 2], cs[k].z);
        atomicAdd(&s_col[d0 + 3], cs[k].w);
    }
    __syncthreads();
    for (int i = tid; i < D_; i += blockDim.x)
        atomicAdd(&g_totsum[b * D_ + i], s_col[i]);
}

// ---------------- K2: exact top-256 (radix select), sorted ascending ----------------
__device__ __forceinline__ unsigned int order_key(float f) {
    unsigned int u = __float_as_uint(f);
    return u ^ ((u >> 31) ? 0xFFFFFFFFu : 0x80000000u);
}

__global__ void k_topk() {
    const int b   = blockIdx.x;
    const int tid = threadIdx.x;
    const int nt  = blockDim.x;

    __shared__ unsigned int skeys[LC_];
    __shared__ int          eqbuf[LC_];
    __shared__ unsigned int hist[256];
    __shared__ int          out_idx[KEEP_];
    __shared__ unsigned int s_prefix;
    __shared__ int          s_krem, s_ngt, s_neq;

    for (int i = tid; i < LC_; i += nt)
        skeys[i] = order_key(g_sal[b * LC_ + i]);
    if (tid == 0) { s_prefix = 0u; s_krem = KEEP_; s_ngt = 0; s_neq = 0; }
    __syncthreads();

    // 4-pass radix select (MSB -> LSB), selecting KEEP_ largest keys
    for (int pass = 0; pass < 4; pass++) {
        const int shift = 24 - 8 * pass;
        for (int i = tid; i < 256; i += nt) hist[i] = 0u;
        __syncthreads();
        const unsigned int pfx = s_prefix;
        for (int i = tid; i < LC_; i += nt) {
            unsigned int k = skeys[i];
            if (pass == 0 || (k >> (shift + 8)) == pfx)
                atomicAdd(&hist[(k >> shift) & 255u], 1u);
        }
        __syncthreads();
        if (tid == 0) {
            int cum = 0, krem = s_krem, sel = 0;
            for (int d = 255; d >= 0; d--) {
                cum += (int)hist[d];
                if (cum >= krem) { sel = d; s_krem = krem - (cum - (int)hist[d]); break; }
            }
            s_prefix = (pfx << 8) | (unsigned int)sel;
        }
        __syncthreads();
    }

    const unsigned int thr = s_prefix;  // exact 32-bit threshold key
    const int rem = s_krem;             // how many == thr to take (lowest indices)

    for (int i = tid; i < LC_; i += nt) {
        unsigned int k = skeys[i];
        if (k > thr)       { int p = atomicAdd(&s_ngt, 1); out_idx[p] = i; }
        else if (k == thr) { int p = atomicAdd(&s_neq, 1); eqbuf[p]   = i; }
    }
    __syncthreads();
    const int ngt = s_ngt, neq = s_neq;
    // pick the `rem` smallest-index elements among the == thr set (matches lax.top_k stability)
    for (int j = tid; j < neq; j += nt) {
        int v = eqbuf[j], c = 0;
        for (int m = 0; m < neq; m++) c += (eqbuf[m] < v);
        if (c < rem) out_idx[ngt + c] = v;
    }
    __syncthreads();

    // bitonic sort 256 indices ascending
    for (int k = 2; k <= KEEP_; k <<= 1) {
        for (int j = k >> 1; j > 0; j >>= 1) {
            for (int t = tid; t < KEEP_; t += nt) {
                int partner = t ^ j;
                if (partner > t) {
                    int a0 = out_idx[t], a1 = out_idx[partner];
                    bool up = ((t & k) == 0);
                    if ((a0 > a1) == up) { out_idx[t] = a1; out_idx[partner] = a0; }
                }
            }
            __syncthreads();
        }
    }
    for (int t = tid; t < KEEP_; t += nt)
        g_topidx[b * KEEP_ + t] = out_idx[t];
}

// ---------------- K3: gather kept rows -> new_active + kept column sums ----------------
// grid: (8, B_), block 256; 32 rows per block
__global__ void k_gather(const float* __restrict__ x,
                         const float* __restrict__ active,
                         float* __restrict__ new_active_out) {
    const int b    = blockIdx.y;
    const int row0 = blockIdx.x * 32;
    const int tid  = threadIdx.x;
    const int e4   = tid * 4;

    float4 s = make_float4(0.f, 0.f, 0.f, 0.f);
    for (int r = 0; r < 32; r++) {
        const int idx = g_topidx[b * KEEP_ + row0 + r];
        const float* src = (idx < A_)
            ? active + ((size_t)b * A_ + idx) * D_
            : x      + ((size_t)b * L_ + (idx - A_)) * D_;
        float4 v = *(const float4*)(src + e4);
        *(float4*)(new_active_out + ((size_t)b * KEEP_ + row0 + r) * D_ + e4) = v;
        s.x += v.x; s.y += v.y; s.z += v.z; s.w += v.w;
    }
    atomicAdd(&g_keptsum[b * D_ + e4 + 0], s.x);
    atomicAdd(&g_keptsum[b * D_ + e4 + 1], s.y);
    atomicAdd(&g_keptsum[b * D_ + e4 + 2], s.z);
    atomicAdd(&g_keptsum[b * D_ + e4 + 3], s.w);
}

// ---------------- K4: cold_new + ctx ----------------
// grid B_, block 1024
__global__ void k_ctx(const float* __restrict__ cold,
                      float* __restrict__ cold_out) {
    const int i = blockIdx.x * D_ + threadIdx.x;
    const float tot = g_totsum[i];
    const float ks  = g_keptsum[i];
    const float dropped_mean = (tot - ks) * (1.0f / (float)(LC_ - KEEP_));
    const float cn = 0.9f * cold[i] + 0.1f * dropped_mean;
    cold_out[i] = cn;
    g_ctx[i] = ks * (1.0f / (float)KEEP_) + cn;
}

// ---------------- K5: proj[b,e] = sum_d ctx[b,d] * w_read[e,d]  (8 batches fused) ----------------
// grid 32, block 256 (8 warps, 4 rows each)
__global__ void k_gemv(const float* __restrict__ wread) {
    __shared__ float4 sctx[B_ * 256];  // 8 batches x 1024 floats
    const int tid = threadIdx.x;
    for (int i = tid; i < B_ * 256; i += blockDim.x)
        sctx[i] = *(const float4*)(g_ctx + i * 4);
    __syncthreads();

    const int warp = tid >> 5, lane = tid & 31;
    for (int r = 0; r < 4; r++) {
        const int e = blockIdx.x * 32 + warp * 4 + r;
        const float* wr = wread + (size_t)e * D_;
        float acc[B_];
#pragma unroll
        for (int bb = 0; bb < B_; bb++) acc[bb] = 0.f;
#pragma unroll
        for (int k = 0; k < 8; k++) {
            float4 w = *(const float4*)(wr + k * 128 + lane * 4);
#pragma unroll
            for (int bb = 0; bb < B_; bb++) {
                float4 c = sctx[bb * 256 + k * 32 + lane];
                acc[bb] += w.x * c.x + w.y * c.y + w.z * c.z + w.w * c.w;
            }
        }
#pragma unroll
        for (int bb = 0; bb < B_; bb++) {
#pragma unroll
            for (int o = 16; o > 0; o >>= 1)
                acc[bb] += __shfl_down_sync(0xffffffffu, acc[bb], o);
            if (lane == 0) g_proj[bb * D_ + e] = acc[bb];
        }
    }
}

// ---------------- K6: x_out = x + proj (broadcast over l) ----------------
// grid: (L_/16, B_), block 256; 16 rows per block
__global__ void k_addproj(const float* __restrict__ x,
                          float* __restrict__ xout) {
    const int b   = blockIdx.y;
    const int l0  = blockIdx.x * 16;
    const int tid = threadIdx.x;
    const float4 p = *(const float4*)(g_proj + b * D_ + tid * 4);
    const float* xs = x    + ((size_t)b * L_ + l0) * D_;
    float*       os = xout + ((size_t)b * L_ + l0) * D_;
#pragma unroll 4
    for (int r = 0; r < 16; r++) {
        float4 v = *(const float4*)(xs + (size_t)r * D_ + tid * 4);
        v.x += p.x; v.y += p.y; v.z += p.z; v.w += p.w;
        *(float4*)(os + (size_t)r * D_ + tid * 4) = v;
    }
}

// ---------------- launch ----------------
extern "C" void kernel_launch(void* const* d_in, const int* in_sizes, int n_in,
                              void* d_out, int out_size) {
    const float* x      = (const float*)d_in[0];   // [8,4096,1024]
    const float* active = (const float*)d_in[1];   // [8,256,1024]
    const float* cold   = (const float*)d_in[2];   // [8,1024]
    const float* w_sal  = (const float*)d_in[3];   // [1024]
    const float* w_read = (const float*)d_in[4];   // [1024,1024]

    float* xout       = (float*)d_out;
    float* new_active = xout + (size_t)in_sizes[0];                    // after x_out
    float* cold_out   = new_active + (size_t)in_sizes[1];              // after new_active

    k_zero<<<(B_ * D_ + 1023) / 1024, 1024>>>();
    {
        dim3 grid(32, B_);
        k_salience<<<grid, 256>>>(x, active, w_sal);
    }
    k_topk<<<B_, 512>>>();
    {
        dim3 grid(8, B_);
        k_gather<<<grid, 256>>>(x, active, new_active);
    }
    k_ctx<<<B_, 1024>>>(cold, cold_out);
    k_gemv<<<32, 256>>>(w_read);
    {
        dim3 grid(L_ / 16, B_);
        k_addproj<<<grid, 256>>>(x, xout);
    }
}